// round 10
// baseline (speedup 1.0000x reference)
#include <cuda_runtime.h>

// Decoder: T_IN=12, B=65536, H=64, T_OUT=12, OVERLAP=3
// 128 threads / 16 batches per CTA.
//   Phase A: 8-lane group owns one batch, lane owns 8 dims, f32x2 math.
//            Writes hA (fp32) AND a pre-converted tf32 A-fragment buffer.
//   Phase B: tf32 mma.sync.m16n8k8; A-frags via conflict-free LDS.64 from
//            the tf32 buffer; B-frags (W_hh) packed as uint4 kt-pairs.
// MMA accumulation order identical to prior round (bit-identical numerics).

#define FULLMASK 0xFFFFFFFFu

constexpr int T_IN  = 12;
constexpr int T_OUT = 12;
constexpr int Bz    = 65536;
constexpr int WARPS = 4;
constexpr int THREADS = WARPS * 32;
constexpr int BPC   = 16;            // batches per CTA
constexpr int HPAD  = 68;            // fp32 h row pitch (floats)
constexpr int APITCH = 36;           // tf32 A-buffer pitch in uint2 (72 words)

// SMEM float offsets
constexpr int WFR_N    = 4 * 6 * 4 * 32;        // warps x nt x ktp x lane (uint4)
constexpr int OFF_ATF  = WFR_N * 4;             // 12288
constexpr int OFF_HA   = OFF_ATF + BPC * APITCH * 2;  // +1152
constexpr int OFF_HG   = OFF_HA + BPC * HPAD;   // +1088
constexpr int OFF_L    = OFF_HG + BPC * HPAD;   // +1088
constexpr int OFF_GP   = OFF_L + BPC * 4;
constexpr int OFF_BH   = OFF_GP + 192 * 4;
constexpr int OFF_WL   = OFF_BH + 192;
constexpr int SMEM_FLOATS = OFF_WL + 64;
constexpr int SMEM_BYTES  = SMEM_FLOATS * 4;    // ~66.8 KB -> 2 CTAs/SM

typedef unsigned long long u64;

__device__ __forceinline__ void ffma2(u64& d, u64 a, u64 b) {
    asm("fma.rn.f32x2 %0, %1, %2, %0;" : "+l"(d) : "l"(a), "l"(b));
}
__device__ __forceinline__ u64 packf2(float lo, float hi) {
    u64 r;
    asm("mov.b64 %0, {%1, %2};" : "=l"(r) : "f"(lo), "f"(hi));
    return r;
}
__device__ __forceinline__ float f2lo(u64 v) {
    return __uint_as_float((unsigned)(v & 0xFFFFFFFFull));
}
__device__ __forceinline__ float f2hi(u64 v) {
    return __uint_as_float((unsigned)(v >> 32));
}
__device__ __forceinline__ float dotp(const u64* a, const u64* b) {
    u64 d = 0ull;
    ffma2(d, a[0], b[0]); ffma2(d, a[1], b[1]);
    ffma2(d, a[2], b[2]); ffma2(d, a[3], b[3]);
    return f2lo(d) + f2hi(d);
}
__device__ __forceinline__ unsigned cvt_tf32(float x) {
    unsigned r;
    asm("cvt.rna.tf32.f32 %0, %1;" : "=r"(r) : "f"(x));
    return r;
}
__device__ __forceinline__ void mma_tf32(float& d0, float& d1, float& d2, float& d3,
                                         unsigned a0, unsigned a1, unsigned a2, unsigned a3,
                                         unsigned b0, unsigned b1) {
    asm("mma.sync.aligned.m16n8k8.row.col.f32.tf32.tf32.f32 "
        "{%0,%1,%2,%3}, {%4,%5,%6,%7}, {%8,%9}, {%0,%1,%2,%3};"
        : "+f"(d0), "+f"(d1), "+f"(d2), "+f"(d3)
        : "r"(a0), "r"(a1), "r"(a2), "r"(a3), "r"(b0), "r"(b1));
}
__device__ __forceinline__ float sigf(float x) {
    return __fdividef(1.0f, 1.0f + __expf(-x));
}
__device__ __forceinline__ float tanhfast(float x) {
    return __fdividef(2.0f, 1.0f + __expf(-2.0f * x)) - 1.0f;
}

__global__ void __launch_bounds__(THREADS, 2)
decoder_kernel(const float* __restrict__ enc,    // (12, B, 64)
               const float* __restrict__ hid0,   // (B, 64)
               const float* __restrict__ last,   // (B, 3)
               const float* __restrict__ Wih,    // (192, 3)
               const float* __restrict__ Whh,    // (192, 64)
               const float* __restrict__ bih,    // (192)
               const float* __restrict__ bhh,    // (192)
               const float* __restrict__ Wlin,   // (1, 64)
               const float* __restrict__ blin,   // (1)
               float* __restrict__ out)          // (B, 12)
{
    extern __shared__ float smem[];
    uint4*  Wfr  = reinterpret_cast<uint4*>(smem);
    uint2*  atf  = reinterpret_cast<uint2*>(smem + OFF_ATF);
    float*  hAsh = smem + OFF_HA;
    float*  hGsh = smem + OFF_HG;
    float4* Lsh  = reinterpret_cast<float4*>(smem + OFF_L);
    float4* gpsh = reinterpret_cast<float4*>(smem + OFF_GP);   // {wih0,1,2,bih}
    float*  bhsh = smem + OFF_BH;
    float*  wlsh = smem + OFF_WL;

    const int tid  = threadIdx.x;
    const int lane = tid & 31;
    const int w    = tid >> 5;
    const int cb0  = blockIdx.x * BPC;

    // ---- stage W_hh into uint4 kt-pair B-fragment layout (tf32), once ----
    // Wfr[((ww*6+nt)*4+ktp)*32+ln] = {b0(kt0),b1(kt0),b0(kt1),b1(kt1)}
    // kt0 = 2*ktp, kt1 = 2*ktp+1; j = (nt>>1)*64 + ww*16 + (nt&1)*8 + (ln>>2)
    for (int i = tid; i < WFR_N; i += THREADS) {
        int ww  = i / 768;
        int rem = i - ww * 768;
        int nt  = rem >> 7;
        int rm2 = rem & 127;
        int ktp = rm2 >> 5;
        int ln  = rm2 & 31;
        int gg  = ln >> 2, t4 = ln & 3;
        int j   = ((nt >> 1) << 6) + ww * 16 + ((nt & 1) << 3) + gg;
        int k0  = ktp * 16;  // kt0*8
        Wfr[i] = make_uint4(cvt_tf32(__ldg(&Whh[j * 64 + k0 + t4])),
                            cvt_tf32(__ldg(&Whh[j * 64 + k0 + t4 + 4])),
                            cvt_tf32(__ldg(&Whh[j * 64 + k0 + 8 + t4])),
                            cvt_tf32(__ldg(&Whh[j * 64 + k0 + 8 + t4 + 4])));
    }
    // ---- stage params ----
    for (int j = tid; j < 192; j += THREADS) {
        gpsh[j] = make_float4(__ldg(&Wih[j * 3 + 0]), __ldg(&Wih[j * 3 + 1]),
                              __ldg(&Wih[j * 3 + 2]), __ldg(&bih[j]));
        bhsh[j] = __ldg(&bhh[j]);
    }
    if (tid < 64) wlsh[tid] = __ldg(&Wlin[tid]);
    // ---- stage hG = hid0 (padded rows), Lsh = last ----
    {
        const float4* hid04 = reinterpret_cast<const float4*>(hid0);
        for (int i = tid; i < BPC * 16; i += THREADS) {
            int b = i >> 4, c = i & 15;
            *reinterpret_cast<float4*>(hGsh + b * HPAD + c * 4) =
                __ldg(&hid04[(cb0 + b) * 16 + c]);
        }
    }
    if (tid < BPC) {
        int gb = cb0 + tid;
        Lsh[tid] = make_float4(__ldg(&last[gb * 3 + 0]),
                               __ldg(&last[gb * 3 + 1]),
                               __ldg(&last[gb * 3 + 2]), 0.0f);
    }

    // ---- Phase A identity: 8-lane group -> one batch, lane -> 8 dims
    const int sub = lane >> 3, lg = lane & 7;
    const int bA  = w * 4 + sub;
    const int gbA = cb0 + bA;
    const float bl = __ldg(blin);

    // encoder slice in registers as f32x2 pairs: 12 t x 4 u64
    const ulonglong2* enc2 = reinterpret_cast<const ulonglong2*>(enc);
    u64 ev[T_IN][4];
#pragma unroll
    for (int t = 0; t < T_IN; t++) {
        int idx = (t * Bz + gbA) * 16 + lg * 2;
        ulonglong2 a = __ldg(&enc2[idx]);
        ulonglong2 b = __ldg(&enc2[idx + 1]);
        ev[t][0] = a.x; ev[t][1] = a.y; ev[t][2] = b.x; ev[t][3] = b.y;
    }

    // ---- Phase B identity: MMA fragment coords
    const int g  = lane >> 2;     // groupID 0..7
    const int t4 = lane & 3;      // threadID-in-group

    __syncthreads();

    // W_lin as f32x2 pairs (per-lane constant)
    u64 wlp[4];
    {
        const ulonglong2* wl2 = reinterpret_cast<const ulonglong2*>(wlsh);
        ulonglong2 a = wl2[lg * 2], b = wl2[lg * 2 + 1];
        wlp[0] = a.x; wlp[1] = a.y; wlp[2] = b.x; wlp[3] = b.y;
    }

#pragma unroll 1
    for (int step = 0; step < T_OUT; step++) {
        // ================= Phase A: out(step-1) + attention =================
        u64 hp[4];
        {
            const ulonglong2* hg2 =
                reinterpret_cast<const ulonglong2*>(hGsh + bA * HPAD + lg * 8);
            ulonglong2 a = hg2[0], b = hg2[1];
            hp[0] = a.x; hp[1] = a.y; hp[2] = b.x; hp[3] = b.y;
        }

        if (step > 0) {
            float o = dotp(hp, wlp);
            o += __shfl_xor_sync(FULLMASK, o, 4);
            o += __shfl_xor_sync(FULLMASK, o, 2);
            o += __shfl_xor_sync(FULLMASK, o, 1);
            o += bl;
            if (lg == 0) {
                float4 L = Lsh[bA];
                out[gbA * T_OUT + step - 1] = o;
                Lsh[bA] = make_float4(o, L.x, L.y, 0.0f);
            }
        }

        float p[T_IN];
#pragma unroll
        for (int t = 0; t < T_IN; t++)
            p[t] = dotp(ev[t], hp);
#pragma unroll
        for (int off = 4; off > 0; off >>= 1)
#pragma unroll
            for (int t = 0; t < T_IN; t++)
                p[t] += __shfl_xor_sync(FULLMASK, p[t], off);

        float m = p[0];
#pragma unroll
        for (int t = 1; t < T_IN; t++) m = fmaxf(m, p[t]);
        float s = 0.0f;
#pragma unroll
        for (int t = 0; t < T_IN; t++) { p[t] = __expf(p[t] - m); s += p[t]; }
        float inv = __fdividef(1.0f, s);

        u64 cp[4] = {0ull, 0ull, 0ull, 0ull};
#pragma unroll
        for (int t = 0; t < T_IN; t++) {
            u64 pp = packf2(p[t], p[t]);
            ffma2(cp[0], ev[t][0], pp); ffma2(cp[1], ev[t][1], pp);
            ffma2(cp[2], ev[t][2], pp); ffma2(cp[3], ev[t][3], pp);
        }
        u64 ip = packf2(inv, inv);
        ffma2(hp[0], cp[0], ip); ffma2(hp[1], cp[1], ip);
        ffma2(hp[2], cp[2], ip); ffma2(hp[3], cp[3], ip);

        // fp32 hA (for hprev in gates)
        {
            ulonglong2* ha2 =
                reinterpret_cast<ulonglong2*>(hAsh + bA * HPAD + lg * 8);
            ha2[0] = make_ulonglong2(hp[0], hp[1]);
            ha2[1] = make_ulonglong2(hp[2], hp[3]);
        }
        // tf32 A-fragment copy: [bat][kt=lg][t4] = {tf32(h[t4]), tf32(h[t4+4])}
        {
            float h0v = f2lo(hp[0]), h1v = f2hi(hp[0]);
            float h2v = f2lo(hp[1]), h3v = f2hi(hp[1]);
            float h4v = f2lo(hp[2]), h5v = f2hi(hp[2]);
            float h6v = f2lo(hp[3]), h7v = f2hi(hp[3]);
            uint4* dst = reinterpret_cast<uint4*>(atf + bA * APITCH + lg * 4);
            dst[0] = make_uint4(cvt_tf32(h0v), cvt_tf32(h4v),
                                cvt_tf32(h1v), cvt_tf32(h5v));
            dst[1] = make_uint4(cvt_tf32(h2v), cvt_tf32(h6v),
                                cvt_tf32(h3v), cvt_tf32(h7v));
        }
        __syncthreads();

        // ============ Phase B: gh = hA @ W_hh^T via tf32 MMA ============
        float acc[6][4];
#pragma unroll
        for (int nt = 0; nt < 6; nt++)
#pragma unroll
            for (int ci = 0; ci < 4; ci++) acc[nt][ci] = 0.0f;

#pragma unroll
        for (int ktp = 0; ktp < 4; ktp++) {
            int kt0 = 2 * ktp;
            // A frags: uint2 {a0,a2} for batch row g; {a1,a3} for row g+8
            uint2 A0g0 = atf[g * APITCH + kt0 * 4 + t4];
            uint2 A0g8 = atf[(g + 8) * APITCH + kt0 * 4 + t4];
            uint2 A1g0 = atf[g * APITCH + kt0 * 4 + 4 + t4];
            uint2 A1g8 = atf[(g + 8) * APITCH + kt0 * 4 + 4 + t4];
#pragma unroll
            for (int nt = 0; nt < 6; nt++) {
                uint4 bv = Wfr[(((w * 6) + nt) * 4 + ktp) * 32 + lane];
                mma_tf32(acc[nt][0], acc[nt][1], acc[nt][2], acc[nt][3],
                         A0g0.x, A0g8.x, A0g0.y, A0g8.y, bv.x, bv.y);
                mma_tf32(acc[nt][0], acc[nt][1], acc[nt][2], acc[nt][3],
                         A1g0.x, A1g8.x, A1g0.y, A1g8.y, bv.z, bv.w);
            }
        }

        // ---- gates: lane covers batches {g, g+8} x dims {w16+ntp8+2t4, +1}
        float4 Lg0 = Lsh[g];
        float4 Lg8 = Lsh[g + 8];
#pragma unroll
        for (int ntp = 0; ntp < 2; ntp++) {
#pragma unroll
            for (int d01 = 0; d01 < 2; d01++) {
                int dim = w * 16 + ntp * 8 + 2 * t4 + d01;
                float4 gpr = gpsh[dim];
                float4 gpz = gpsh[64 + dim];
                float4 gpn = gpsh[128 + dim];
                float bhr = bhsh[dim], bhz = bhsh[64 + dim], bhn = bhsh[128 + dim];
#pragma unroll
                for (int bb = 0; bb < 2; bb++) {
                    int bat = g + 8 * bb;
                    float4 L = bb ? Lg8 : Lg0;
                    int ci = bb * 2 + d01;
                    float ghr = acc[ntp][ci]     + bhr;
                    float ghz = acc[ntp + 2][ci] + bhz;
                    float ghn = acc[ntp + 4][ci] + bhn;
                    float gir = fmaf(gpr.x, L.x, fmaf(gpr.y, L.y, fmaf(gpr.z, L.z, gpr.w)));
                    float giz = fmaf(gpz.x, L.x, fmaf(gpz.y, L.y, fmaf(gpz.z, L.z, gpz.w)));
                    float gin = fmaf(gpn.x, L.x, fmaf(gpn.y, L.y, fmaf(gpn.z, L.z, gpn.w)));
                    float r = sigf(gir + ghr);
                    float z = sigf(giz + ghz);
                    float n = tanhfast(fmaf(r, ghn, gin));
                    float hprev = hAsh[bat * HPAD + dim];
                    hGsh[bat * HPAD + dim] = fmaf(z, hprev - n, n);
                }
            }
        }
        __syncthreads();
    }

    // ---- final output (step T_OUT-1) from hG ----
    {
        u64 hp[4];
        const ulonglong2* hg2 =
            reinterpret_cast<const ulonglong2*>(hGsh + bA * HPAD + lg * 8);
        ulonglong2 a = hg2[0], b = hg2[1];
        hp[0] = a.x; hp[1] = a.y; hp[2] = b.x; hp[3] = b.y;
        float o = dotp(hp, wlp);
        o += __shfl_xor_sync(FULLMASK, o, 4);
        o += __shfl_xor_sync(FULLMASK, o, 2);
        o += __shfl_xor_sync(FULLMASK, o, 1);
        o += bl;
        if (lg == 0) out[gbA * T_OUT + T_OUT - 1] = o;
    }
}

extern "C" void kernel_launch(void* const* d_in, const int* in_sizes, int n_in,
                              void* d_out, int out_size) {
    const float* enc  = (const float*)d_in[0];
    const float* hid0 = (const float*)d_in[1];
    const float* last = (const float*)d_in[2];
    const float* Wih  = (const float*)d_in[3];
    const float* Whh  = (const float*)d_in[4];
    const float* bih  = (const float*)d_in[5];
    const float* bhh  = (const float*)d_in[6];
    const float* Wlin = (const float*)d_in[7];
    const float* blin = (const float*)d_in[8];
    float* out = (float*)d_out;

    cudaFuncSetAttribute(decoder_kernel,
                         cudaFuncAttributeMaxDynamicSharedMemorySize,
                         SMEM_BYTES);

    dim3 grid(Bz / BPC);   // 4096 CTAs
    decoder_kernel<<<grid, THREADS, SMEM_BYTES>>>(
        enc, hid0, last, Wih, Whh, bih, bhh, Wlin, blin, out);
}